// round 9
// baseline (speedup 1.0000x reference)
#include <cuda_runtime.h>
#include <cuda_bf16.h>
#include <cstdint>

// Problem constants
#define VOCAB   100000
#define EMBED   128
#define BATCH   64
#define SEQLEN  2048
#define NCHUNK  16
#define CHUNK   (SEQLEN / NCHUNK)   // 128 tokens per block
#define TILE    64                  // rows per bulk round (32 KB smem tile)
#define NROUND  (CHUNK / TILE)      // 2

// Device scratch (zero-initialized at load; every execution restores the
// all-zero invariant, so graph replays are deterministic).
__device__ float g_sums[BATCH * EMBED];
__device__ int   g_count[BATCH];

// ---- bulk-async / mbarrier helpers (inline PTX, no header deps) ------------
__device__ __forceinline__ void mbar_init(uint32_t mbar, uint32_t count) {
    asm volatile("mbarrier.init.shared.b64 [%0], %1;" :: "r"(mbar), "r"(count) : "memory");
}
__device__ __forceinline__ void mbar_expect_tx(uint32_t mbar, uint32_t bytes) {
    asm volatile("mbarrier.arrive.expect_tx.shared.b64 _, [%0], %1;"
                 :: "r"(mbar), "r"(bytes) : "memory");
}
__device__ __forceinline__ void mbar_wait(uint32_t mbar, uint32_t parity) {
    asm volatile(
        "{\n\t"
        ".reg .pred P;\n\t"
        "WAIT_%=:\n\t"
        "mbarrier.try_wait.parity.acquire.cta.shared::cta.b64 P, [%0], %1, 0x989680;\n\t"
        "@P bra.uni DONE_%=;\n\t"
        "bra.uni WAIT_%=;\n\t"
        "DONE_%=:\n\t"
        "}"
        :: "r"(mbar), "r"(parity) : "memory");
}
// Non-tensor bulk copy gmem->smem through the TMA/UBLKCP path.
// src/dst 16B-aligned, size multiple of 16.
__device__ __forceinline__ void bulk_g2s(uint32_t smem_dst, const void* gmem_src,
                                         uint32_t bytes, uint32_t mbar) {
    asm volatile(
        "cp.async.bulk.shared::cta.global.mbarrier::complete_tx::bytes "
        "[%0], [%1], %2, [%3];"
        :: "r"(smem_dst), "l"(gmem_src), "r"(bytes), "r"(mbar) : "memory");
}

// ---------------------------------------------------------------------------
// Single fused kernel. grid = (NCHUNK, BATCH) = (16, 64) = 1024 blocks x 128.
//
// R5/R6/R8 evidence: LDG and cp.async(LDGSTS) gathers all cap at 2.2-2.7 TB/s
// regardless of occupancy or pipeline depth -> per-SM L1TEX outstanding-miss
// budget (~2 KB in flight). This version issues each 512B embedding row as a
// cp.async.bulk (TMA-unit path, own deep request tracking, LTS-cap capable):
//   round: 64 threads each issue one 512B row into a 32KB smem tile against
//   one mbarrier (expect_tx = 32768), all threads wait parity, then reduce
//   the tile; 2 rounds cover the block's 128 tokens.
// ---------------------------------------------------------------------------
__global__ __launch_bounds__(128) void cbow_fused_kernel(
    const void* __restrict__ xraw,     // [BATCH, SEQLEN] token ids (int64 or int32)
    const float* __restrict__ emb,     // [VOCAB, EMBED] f32
    float* __restrict__ out)           // [BATCH, 4, EMBED] f32
{
    __shared__ float4 tile[TILE][32];             // 32 KB bulk landing tile
    __shared__ int    toks[CHUNK];
    __shared__ float4 part[128];
    __shared__ unsigned long long mbar_storage;
    __shared__ int    s_is64;
    __shared__ int    s_last;

    const int b    = blockIdx.y;
    const int base = blockIdx.x * CHUNK;
    const int tid  = threadIdx.x;
    const int c    = tid & 31;   // float4 column of the 128-float row
    const int g    = tid >> 5;   // row phase (0..3)

    const uint32_t mbar = (uint32_t)__cvta_generic_to_shared(&mbar_storage);
    const uint32_t tile_base = (uint32_t)__cvta_generic_to_shared(&tile[0][0]);

    // ---- Phase 0: dtype detection (warp 0; first 256B safe under both) ----
    if (tid < 32) {
        const long long v = ((const long long*)xraw)[tid];
        const unsigned bad = __ballot_sync(0xFFFFFFFFu, v < 0 || v >= VOCAB);
        if (tid == 0) s_is64 = (bad == 0u);
    }
    if (tid == 0) mbar_init(mbar, 1);
    __syncthreads();
    const int is64 = s_is64;

    // ---- Phase 1: stage this chunk's 128 token ids (clamped int32) ----
    {
        const int idx = b * SEQLEN + base + tid;
        long long v = is64 ? ((const long long*)xraw)[idx]
                           : (long long)((const int*)xraw)[idx];
        if (v < 0) v = 0;
        if (v >= VOCAB) v = VOCAB - 1;
        toks[tid] = (int)v;
    }
    __syncthreads();

    // ---- Phase 2: bulk-async gather rounds ----
    float4 acc = make_float4(0.f, 0.f, 0.f, 0.f);

    #pragma unroll
    for (int r = 0; r < NROUND; r++) {
        if (tid == 0) mbar_expect_tx(mbar, TILE * 512u);
        __syncthreads();  // expect_tx ordered before any completion can land

        if (tid < TILE) {
            const int tok = toks[r * TILE + tid];
            bulk_g2s(tile_base + (uint32_t)tid * 512u,
                     (const char*)emb + (size_t)tok * 512u,
                     512u, mbar);
        }

        mbar_wait(mbar, (uint32_t)(r & 1));

        // Reduce the tile: thread (g,c) reads rows {g, g+4, ..., g+60}, col c.
        // LDS.128 on 512B rows -> natural 4-phase access, conflict-free.
        #pragma unroll
        for (int j = 0; j < TILE / 4; j++) {
            const float4 v = tile[j * 4 + g][c];
            acc.x += v.x; acc.y += v.y; acc.z += v.z; acc.w += v.w;
        }
        __syncthreads();  // all reads done before next round overwrites tile
    }

    part[tid] = acc;
    __syncthreads();

    // ---- Phase 3: reduce the 4 row phases, atomic into per-batch sum ----
    if (g == 0) {
        const float4 p0 = part[c];
        const float4 p1 = part[32 + c];
        const float4 p2 = part[64 + c];
        const float4 p3 = part[96 + c];
        float* dst = &g_sums[b * EMBED + c * 4];
        atomicAdd(dst + 0, p0.x + p1.x + p2.x + p3.x);
        atomicAdd(dst + 1, p0.y + p1.y + p2.y + p3.y);
        atomicAdd(dst + 2, p0.z + p1.z + p2.z + p3.z);
        atomicAdd(dst + 3, p0.w + p1.w + p2.w + p3.w);
    }

    __threadfence();
    __syncthreads();
    if (tid == 0) {
        const int old = atomicAdd(&g_count[b], 1);
        s_last = (old == NCHUNK - 1);
    }
    __syncthreads();

    // ---- Phase 4: last block of this batch finalizes ----
    // Output [B, 4, E], offsets [-1, -2, +1, +2]:
    //   off -1: S - emb[x[L-1]]               + 1*emb[0]
    //   off -2: S - emb[x[L-1]] - emb[x[L-2]] + 2*emb[0]
    //   off +1: S - emb[x[0]]                 + 1*emb[0]
    //   off +2: S - emb[x[0]]   - emb[x[1]]   + 2*emb[0]
    if (s_last) {
        const int e = tid;
        const float S = *(volatile float*)&g_sums[b * EMBED + e];

        long long tf0, tf1, tl0, tl1;
        if (is64) {
            const long long* x64 = (const long long*)xraw;
            tf0 = x64[(size_t)b * SEQLEN + 0];
            tf1 = x64[(size_t)b * SEQLEN + 1];
            tl1 = x64[(size_t)b * SEQLEN + (SEQLEN - 2)];
            tl0 = x64[(size_t)b * SEQLEN + (SEQLEN - 1)];
        } else {
            const int* x32 = (const int*)xraw;
            tf0 = x32[(size_t)b * SEQLEN + 0];
            tf1 = x32[(size_t)b * SEQLEN + 1];
            tl1 = x32[(size_t)b * SEQLEN + (SEQLEN - 2)];
            tl0 = x32[(size_t)b * SEQLEN + (SEQLEN - 1)];
        }
        if (tf0 < 0) tf0 = 0; if (tf0 >= VOCAB) tf0 = VOCAB - 1;
        if (tf1 < 0) tf1 = 0; if (tf1 >= VOCAB) tf1 = VOCAB - 1;
        if (tl0 < 0) tl0 = 0; if (tl0 >= VOCAB) tl0 = VOCAB - 1;
        if (tl1 < 0) tl1 = 0; if (tl1 >= VOCAB) tl1 = VOCAB - 1;

        const float e0 = emb[e];
        const float f0 = emb[(size_t)tf0 * EMBED + e];
        const float f1 = emb[(size_t)tf1 * EMBED + e];
        const float l0 = emb[(size_t)tl0 * EMBED + e];
        const float l1 = emb[(size_t)tl1 * EMBED + e];

        float* o = out + (size_t)b * 4 * EMBED;
        o[0 * EMBED + e] = S - l0 + e0;
        o[1 * EMBED + e] = S - l0 - l1 + 2.0f * e0;
        o[2 * EMBED + e] = S - f0 + e0;
        o[3 * EMBED + e] = S - f0 - f1 + 2.0f * e0;

        // Restore the zero-invariant for the next graph replay.
        g_sums[b * EMBED + e] = 0.0f;
        if (tid == 0) g_count[b] = 0;
    }
}

// ---------------------------------------------------------------------------
// Launch. Input order resolved from element counts:
//   x   : BATCH*SEQLEN = 131072 elements
//   emb : VOCAB*EMBED  = 12800000 elements
// ---------------------------------------------------------------------------
extern "C" void kernel_launch(void* const* d_in, const int* in_sizes, int n_in,
                              void* d_out, int out_size) {
    int ix = 0, ie = 1;
    if (in_sizes[0] != BATCH * SEQLEN) { ix = 1; ie = 0; }

    const void*  x   = d_in[ix];
    const float* emb = (const float*)d_in[ie];
    float*       out = (float*)d_out;

    dim3 grid(NCHUNK, BATCH);
    cbow_fused_kernel<<<grid, 128>>>(x, emb, out);
}

// round 11
// speedup vs baseline: 1.2980x; 1.2980x over previous
#include <cuda_runtime.h>
#include <cuda_bf16.h>
#include <cstdint>

// Problem constants
#define VOCAB   100000
#define EMBED   128
#define BATCH   64
#define SEQLEN  2048
#define NCHUNK  32
#define CHUNK   (SEQLEN / NCHUNK)   // 64 tokens per block

// Device scratch (zero-initialized at load; every execution restores the
// all-zero invariant, so graph replays are deterministic).
__device__ float g_sums[BATCH * EMBED];
__device__ int   g_count[BATCH];

// --- L2 evict_last via createpolicy + cache_hint (general-width form; the
// direct .L2::evict_last qualifier is 32B-only on sm_100 per R10 ptxas). ---
__device__ __forceinline__ unsigned long long l2_evict_last_policy() {
    unsigned long long p;
    asm("createpolicy.fractional.L2::evict_last.b64 %0, 1.0;" : "=l"(p));
    return p;
}
__device__ __forceinline__ float4 ldg_pol4(const float4* p, unsigned long long pol) {
    float4 v;
    asm("ld.global.nc.L2::cache_hint.v4.f32 {%0,%1,%2,%3}, [%4], %5;"
        : "=f"(v.x), "=f"(v.y), "=f"(v.z), "=f"(v.w) : "l"(p), "l"(pol));
    return v;
}
__device__ __forceinline__ float ldg_pol1(const float* p, unsigned long long pol) {
    float v;
    asm("ld.global.nc.L2::cache_hint.f32 %0, [%1], %2;" : "=f"(v) : "l"(p), "l"(pol));
    return v;
}

// ---------------------------------------------------------------------------
// Single fused kernel. grid = (NCHUNK, BATCH) = (32, 64) = 2048 blocks x 128
// (~86% occupancy, single wave). Structure identical to the 12.9us R6 kernel;
// the only change is the L2 evict_last policy on the embedding gather — the
// 51.2MB table fits in ~126MB L2, which persists across graph replays, so
// steady-state timed replays gather from L2 instead of random-512B DRAM.
//
// Phase 0: dtype detect (x may be int64 or int32 depending on jax x64 mode).
// Phase 1: stage 64 tokens into smem (int, clamped).
// Phase 2: gather-accumulate. lane c = tid&31 owns float4 column c of the
//          128-float row (32 x 16B = 512B, coalesced); g = tid>>5 phases
//          tokens by 4; 16 fully-unrolled independent loads.
// Phase 3: smem cross-phase reduce, atomicAdd into g_sums[b].
// Phase 4: last block per batch finalizes from the full-sequence sum +
//          boundary corrections, resets scratch for the next replay.
// ---------------------------------------------------------------------------
__global__ __launch_bounds__(128) void cbow_fused_kernel(
    const void* __restrict__ xraw,     // [BATCH, SEQLEN] token ids (int64 or int32)
    const float* __restrict__ emb,     // [VOCAB, EMBED] f32
    float* __restrict__ out)           // [BATCH, 4, EMBED] f32
{
    __shared__ int    toks[CHUNK];
    __shared__ float4 part[128];
    __shared__ int    s_is64;
    __shared__ int    s_last;

    const int b    = blockIdx.y;
    const int base = blockIdx.x * CHUNK;
    const int tid  = threadIdx.x;

    const unsigned long long pol = l2_evict_last_policy();

    // ---- Phase 0: dtype detection (warp 0; first 256B safe under both) ----
    if (tid < 32) {
        const long long v = ((const long long*)xraw)[tid];
        const unsigned bad = __ballot_sync(0xFFFFFFFFu, v < 0 || v >= VOCAB);
        if (tid == 0) s_is64 = (bad == 0u);
    }
    __syncthreads();
    const int is64 = s_is64;

    // ---- Phase 1: stage tokens (CHUNK=64 -> first 64 threads) ----
    if (tid < CHUNK) {
        const int idx = b * SEQLEN + base + tid;
        long long v = is64 ? ((const long long*)xraw)[idx]
                           : (long long)((const int*)xraw)[idx];
        if (v < 0) v = 0;
        if (v >= VOCAB) v = VOCAB - 1;
        toks[tid] = (int)v;
    }
    __syncthreads();

    // ---- Phase 2: gather-accumulate (16 independent loads, fully unrolled) ----
    const int c = tid & 31;   // float4 column within the 128-float row
    const int g = tid >> 5;   // token phase (0..3)

    float4 acc = make_float4(0.f, 0.f, 0.f, 0.f);
    #pragma unroll
    for (int t = g; t < CHUNK; t += 4) {
        const float4 v = ldg_pol4(
            reinterpret_cast<const float4*>(emb + (size_t)toks[t] * EMBED) + c, pol);
        acc.x += v.x; acc.y += v.y; acc.z += v.z; acc.w += v.w;
    }
    part[tid] = acc;
    __syncthreads();

    // ---- Phase 3: reduce the 4 token phases, atomic into per-batch sum ----
    if (g == 0) {
        const float4 p0 = part[c];
        const float4 p1 = part[32 + c];
        const float4 p2 = part[64 + c];
        const float4 p3 = part[96 + c];
        float* dst = &g_sums[b * EMBED + c * 4];
        atomicAdd(dst + 0, p0.x + p1.x + p2.x + p3.x);
        atomicAdd(dst + 1, p0.y + p1.y + p2.y + p3.y);
        atomicAdd(dst + 2, p0.z + p1.z + p2.z + p3.z);
        atomicAdd(dst + 3, p0.w + p1.w + p2.w + p3.w);
    }

    // Make our atomics visible device-wide before signalling completion.
    __threadfence();
    __syncthreads();
    if (tid == 0) {
        const int old = atomicAdd(&g_count[b], 1);
        s_last = (old == NCHUNK - 1);
    }
    __syncthreads();

    // ---- Phase 4: last block of this batch finalizes ----
    // Output [B, 4, E], offsets [-1, -2, +1, +2]:
    //   off -1: S - emb[x[L-1]]               + 1*emb[0]
    //   off -2: S - emb[x[L-1]] - emb[x[L-2]] + 2*emb[0]
    //   off +1: S - emb[x[0]]                 + 1*emb[0]
    //   off +2: S - emb[x[0]]   - emb[x[1]]   + 2*emb[0]
    if (s_last) {
        const int e = tid;

        // Volatile read: atomics land in L2; bypass any stale L1 line.
        const float S = *(volatile float*)&g_sums[b * EMBED + e];

        long long tf0, tf1, tl0, tl1;
        if (is64) {
            const long long* x64 = (const long long*)xraw;
            tf0 = x64[(size_t)b * SEQLEN + 0];
            tf1 = x64[(size_t)b * SEQLEN + 1];
            tl1 = x64[(size_t)b * SEQLEN + (SEQLEN - 2)];
            tl0 = x64[(size_t)b * SEQLEN + (SEQLEN - 1)];
        } else {
            const int* x32 = (const int*)xraw;
            tf0 = x32[(size_t)b * SEQLEN + 0];
            tf1 = x32[(size_t)b * SEQLEN + 1];
            tl1 = x32[(size_t)b * SEQLEN + (SEQLEN - 2)];
            tl0 = x32[(size_t)b * SEQLEN + (SEQLEN - 1)];
        }
        if (tf0 < 0) tf0 = 0; if (tf0 >= VOCAB) tf0 = VOCAB - 1;
        if (tf1 < 0) tf1 = 0; if (tf1 >= VOCAB) tf1 = VOCAB - 1;
        if (tl0 < 0) tl0 = 0; if (tl0 >= VOCAB) tl0 = VOCAB - 1;
        if (tl1 < 0) tl1 = 0; if (tl1 >= VOCAB) tl1 = VOCAB - 1;

        const float e0 = ldg_pol1(emb + e, pol);  // emb[token 0][e]
        const float f0 = ldg_pol1(emb + (size_t)tf0 * EMBED + e, pol);
        const float f1 = ldg_pol1(emb + (size_t)tf1 * EMBED + e, pol);
        const float l0 = ldg_pol1(emb + (size_t)tl0 * EMBED + e, pol);
        const float l1 = ldg_pol1(emb + (size_t)tl1 * EMBED + e, pol);

        float* o = out + (size_t)b * 4 * EMBED;
        o[0 * EMBED + e] = S - l0 + e0;                  // offset -1
        o[1 * EMBED + e] = S - l0 - l1 + 2.0f * e0;      // offset -2
        o[2 * EMBED + e] = S - f0 + e0;                  // offset +1
        o[3 * EMBED + e] = S - f0 - f1 + 2.0f * e0;      // offset +2

        // Restore the zero-invariant for the next graph replay.
        g_sums[b * EMBED + e] = 0.0f;
        if (tid == 0) g_count[b] = 0;
    }
}

// ---------------------------------------------------------------------------
// Launch. Input order resolved from element counts:
//   x   : BATCH*SEQLEN = 131072 elements
//   emb : VOCAB*EMBED  = 12800000 elements
// ---------------------------------------------------------------------------
extern "C" void kernel_launch(void* const* d_in, const int* in_sizes, int n_in,
                              void* d_out, int out_size) {
    int ix = 0, ie = 1;
    if (in_sizes[0] != BATCH * SEQLEN) { ix = 1; ie = 0; }

    const void*  x   = d_in[ix];
    const float* emb = (const float*)d_in[ie];
    float*       out = (float*)d_out;

    dim3 grid(NCHUNK, BATCH);
    cbow_fused_kernel<<<grid, 128>>>(x, emb, out);
}

// round 12
// speedup vs baseline: 1.3478x; 1.0384x over previous
#include <cuda_runtime.h>
#include <cuda_bf16.h>
#include <cstdint>

// Problem constants
#define VOCAB   100000
#define EMBED   128
#define BATCH   64
#define SEQLEN  2048
#define NCHUNK  16
#define CHUNK   (SEQLEN / NCHUNK)   // 128 tokens per block

// Device scratch (zero-initialized at load; every execution restores the
// all-zero invariant, so graph replays are deterministic).
__device__ float g_sums[BATCH * EMBED];
__device__ int   g_count[BATCH];

// ---------------------------------------------------------------------------
// Single fused kernel. grid = (NCHUNK, BATCH) = (16, 64) = 1024 blocks x 128
// (6.9 blocks/SM, single wave under the 8-block register cap).
//
// New in this round (the depth probe):
//  1. prefetch.global.L2 issued for ALL 32 of a thread's row-chunks before
//     any LDG: prefetches cost no registers and no scoreboard slot, so each
//     warp immediately posts its full request set; the later LDGs merge with
//     the in-flight prefetches instead of starting cold.
//  2. Explicit 8-deep load batches + __launch_bounds__(128, 8) (~64 regs)
//     force ptxas to keep ~8 LDG.128 in flight per warp (the 32-reg builds
//     batched only ~4), with two accumulators to split the FADD chain.
// ---------------------------------------------------------------------------
__global__ __launch_bounds__(128, 8) void cbow_fused_kernel(
    const void* __restrict__ xraw,     // [BATCH, SEQLEN] token ids (int64 or int32)
    const float* __restrict__ emb,     // [VOCAB, EMBED] f32
    float* __restrict__ out)           // [BATCH, 4, EMBED] f32
{
    __shared__ int    toks[CHUNK];
    __shared__ float4 part[128];
    __shared__ int    s_is64;
    __shared__ int    s_last;

    const int b    = blockIdx.y;
    const int base = blockIdx.x * CHUNK;
    const int tid  = threadIdx.x;

    // ---- Phase 0: dtype detection (warp 0; first 256B safe under both) ----
    if (tid < 32) {
        const long long v = ((const long long*)xraw)[tid];
        const unsigned bad = __ballot_sync(0xFFFFFFFFu, v < 0 || v >= VOCAB);
        if (tid == 0) s_is64 = (bad == 0u);
    }
    __syncthreads();
    const int is64 = s_is64;

    // ---- Phase 1: stage this chunk's 128 token ids (clamped int32) ----
    {
        const int idx = b * SEQLEN + base + tid;
        long long v = is64 ? ((const long long*)xraw)[idx]
                           : (long long)((const int*)xraw)[idx];
        if (v < 0) v = 0;
        if (v >= VOCAB) v = VOCAB - 1;
        toks[tid] = (int)v;
    }
    __syncthreads();

    // ---- Phase 2: prefetch-decoupled, deep-batched gather-accumulate ----
    const int c   = tid & 31;   // float4 column within the 128-float row
    const int gph = tid >> 5;   // token phase (0..3); this thread's rows are
                                // t = gph, gph+4, ..., gph+124  (32 rows)

    // 2a: post all 32 requests to L2 up-front (no regs, no scoreboard).
    #pragma unroll
    for (int t = gph; t < CHUNK; t += 4) {
        const float4* p =
            reinterpret_cast<const float4*>(emb + (size_t)toks[t] * EMBED) + c;
        asm volatile("prefetch.global.L2 [%0];" :: "l"(p));
    }

    // 2b: 4 rounds of 8 explicitly-batched loads (8 LDG.128 in flight/warp).
    float4 acc0 = make_float4(0.f, 0.f, 0.f, 0.f);
    float4 acc1 = make_float4(0.f, 0.f, 0.f, 0.f);
    #pragma unroll
    for (int round = 0; round < 4; round++) {
        float4 v[8];
        #pragma unroll
        for (int j = 0; j < 8; j++) {
            const int t = gph + (round * 8 + j) * 4;
            v[j] = __ldg(
                reinterpret_cast<const float4*>(emb + (size_t)toks[t] * EMBED) + c);
        }
        #pragma unroll
        for (int j = 0; j < 8; j += 2) {
            acc0.x += v[j].x;     acc0.y += v[j].y;
            acc0.z += v[j].z;     acc0.w += v[j].w;
            acc1.x += v[j + 1].x; acc1.y += v[j + 1].y;
            acc1.z += v[j + 1].z; acc1.w += v[j + 1].w;
        }
    }
    part[tid] = make_float4(acc0.x + acc1.x, acc0.y + acc1.y,
                            acc0.z + acc1.z, acc0.w + acc1.w);
    __syncthreads();

    // ---- Phase 3: reduce the 4 token phases, atomic into per-batch sum ----
    if (gph == 0) {
        const float4 p0 = part[c];
        const float4 p1 = part[32 + c];
        const float4 p2 = part[64 + c];
        const float4 p3 = part[96 + c];
        float* dst = &g_sums[b * EMBED + c * 4];
        atomicAdd(dst + 0, p0.x + p1.x + p2.x + p3.x);
        atomicAdd(dst + 1, p0.y + p1.y + p2.y + p3.y);
        atomicAdd(dst + 2, p0.z + p1.z + p2.z + p3.z);
        atomicAdd(dst + 3, p0.w + p1.w + p2.w + p3.w);
    }

    // Make our atomics visible device-wide before signalling completion.
    __threadfence();
    __syncthreads();
    if (tid == 0) {
        const int old = atomicAdd(&g_count[b], 1);
        s_last = (old == NCHUNK - 1);
    }
    __syncthreads();

    // ---- Phase 4: last block of this batch finalizes ----
    // Output [B, 4, E], offsets [-1, -2, +1, +2]:
    //   off -1: S - emb[x[L-1]]               + 1*emb[0]
    //   off -2: S - emb[x[L-1]] - emb[x[L-2]] + 2*emb[0]
    //   off +1: S - emb[x[0]]                 + 1*emb[0]
    //   off +2: S - emb[x[0]]   - emb[x[1]]   + 2*emb[0]
    if (s_last) {
        const int e = tid;

        // Volatile read: atomics land in L2; bypass any stale L1 line.
        const float S = *(volatile float*)&g_sums[b * EMBED + e];

        long long tf0, tf1, tl0, tl1;
        if (is64) {
            const long long* x64 = (const long long*)xraw;
            tf0 = x64[(size_t)b * SEQLEN + 0];
            tf1 = x64[(size_t)b * SEQLEN + 1];
            tl1 = x64[(size_t)b * SEQLEN + (SEQLEN - 2)];
            tl0 = x64[(size_t)b * SEQLEN + (SEQLEN - 1)];
        } else {
            const int* x32 = (const int*)xraw;
            tf0 = x32[(size_t)b * SEQLEN + 0];
            tf1 = x32[(size_t)b * SEQLEN + 1];
            tl1 = x32[(size_t)b * SEQLEN + (SEQLEN - 2)];
            tl0 = x32[(size_t)b * SEQLEN + (SEQLEN - 1)];
        }
        if (tf0 < 0) tf0 = 0; if (tf0 >= VOCAB) tf0 = VOCAB - 1;
        if (tf1 < 0) tf1 = 0; if (tf1 >= VOCAB) tf1 = VOCAB - 1;
        if (tl0 < 0) tl0 = 0; if (tl0 >= VOCAB) tl0 = VOCAB - 1;
        if (tl1 < 0) tl1 = 0; if (tl1 >= VOCAB) tl1 = VOCAB - 1;

        const float e0 = emb[e];  // emb[token 0][e]
        const float f0 = emb[(size_t)tf0 * EMBED + e];
        const float f1 = emb[(size_t)tf1 * EMBED + e];
        const float l0 = emb[(size_t)tl0 * EMBED + e];
        const float l1 = emb[(size_t)tl1 * EMBED + e];

        float* o = out + (size_t)b * 4 * EMBED;
        o[0 * EMBED + e] = S - l0 + e0;                  // offset -1
        o[1 * EMBED + e] = S - l0 - l1 + 2.0f * e0;      // offset -2
        o[2 * EMBED + e] = S - f0 + e0;                  // offset +1
        o[3 * EMBED + e] = S - f0 - f1 + 2.0f * e0;      // offset +2

        // Restore the zero-invariant for the next graph replay.
        g_sums[b * EMBED + e] = 0.0f;
        if (tid == 0) g_count[b] = 0;
    }
}

// ---------------------------------------------------------------------------
// Launch. Input order resolved from element counts:
//   x   : BATCH*SEQLEN = 131072 elements
//   emb : VOCAB*EMBED  = 12800000 elements
// ---------------------------------------------------------------------------
extern "C" void kernel_launch(void* const* d_in, const int* in_sizes, int n_in,
                              void* d_out, int out_size) {
    int ix = 0, ie = 1;
    if (in_sizes[0] != BATCH * SEQLEN) { ix = 1; ie = 0; }

    const void*  x   = d_in[ix];
    const float* emb = (const float*)d_in[ie];
    float*       out = (float*)d_out;

    dim3 grid(NCHUNK, BATCH);
    cbow_fused_kernel<<<grid, 128>>>(x, emb, out);
}